// round 11
// baseline (speedup 1.0000x reference)
#include <cuda_runtime.h>
#include <cuda_bf16.h>

#define T_SEQ   2049
#define D_MODEL 1024
#define NHEAD   16
#define HDIM    64

// ---------------------------------------------------------------------------
// Scratch (static __device__ — no allocation anywhere, per harness rules)
// ---------------------------------------------------------------------------
__device__ float g_qh[(size_t)NHEAD * T_SEQ * HDIM];                 // (H,T,HD)
__device__ float g_kh[(size_t)NHEAD * T_SEQ * HDIM];
__device__ float g_vh[(size_t)NHEAD * T_SEQ * HDIM];
__device__ float g_S [(size_t)NHEAD * T_SEQ * T_SEQ];                // (H,T,T) scores/probs
__device__ float g_ctx[(size_t)T_SEQ * D_MODEL];                     // (T,D)

// ---------------------------------------------------------------------------
// NT GEMM: C[m][n] = sum_k A[m][k] * W[n][k] + bias[n]
// A: (M=2049, K=1024) row-major; W: (1024, 1024) row-major.
// SCATTER=1: write to head-major (H,T,HD) layout for qh/kh/vh
// SCATTER=0: write plain row-major (final output projection)
// 64x64 tile, 16 k-slab, 256 threads, 4x4 per thread, float4 smem reads.
// ---------------------------------------------------------------------------
template<int SCATTER>
__global__ __launch_bounds__(256)
void gemm_nt_kernel(const float* __restrict__ A, const float* __restrict__ W,
                    const float* __restrict__ bias, float* __restrict__ out) {
    __shared__ float As[16][68];
    __shared__ float Bs[16][68];
    const int M = T_SEQ, K = D_MODEL;
    const int m0 = blockIdx.y * 64;
    const int n0 = blockIdx.x * 64;
    const int tid = threadIdx.x;
    const int tx = tid & 15, ty = tid >> 4;
    const int lrow = tid >> 2;
    const int lk   = (tid & 3) * 4;

    float acc[4][4] = {};
    const bool arow_ok = (m0 + lrow) < M;
    const float* aptr = A + (size_t)(m0 + lrow) * K + lk;
    const float* wptr = W + (size_t)(n0 + lrow) * K + lk;

    for (int k0 = 0; k0 < K; k0 += 16) {
        float4 va = arow_ok ? *(const float4*)(aptr + k0)
                            : make_float4(0.f, 0.f, 0.f, 0.f);
        float4 vb = *(const float4*)(wptr + k0);
        As[lk+0][lrow] = va.x; As[lk+1][lrow] = va.y;
        As[lk+2][lrow] = va.z; As[lk+3][lrow] = va.w;
        Bs[lk+0][lrow] = vb.x; Bs[lk+1][lrow] = vb.y;
        Bs[lk+2][lrow] = vb.z; Bs[lk+3][lrow] = vb.w;
        __syncthreads();
#pragma unroll
        for (int kk = 0; kk < 16; kk++) {
            float4 a4 = *(const float4*)&As[kk][ty * 4];
            float4 b4 = *(const float4*)&Bs[kk][tx * 4];
            float a[4] = {a4.x, a4.y, a4.z, a4.w};
            float b[4] = {b4.x, b4.y, b4.z, b4.w};
#pragma unroll
            for (int i = 0; i < 4; i++)
#pragma unroll
                for (int j = 0; j < 4; j++)
                    acc[i][j] = fmaf(a[i], b[j], acc[i][j]);
        }
        __syncthreads();
    }

#pragma unroll
    for (int i = 0; i < 4; i++) {
        int m = m0 + ty * 4 + i;
        if (m >= M) continue;
#pragma unroll
        for (int j = 0; j < 4; j++) {
            int n = n0 + tx * 4 + j;
            float v = acc[i][j] + bias[n];
            if (SCATTER)
                out[(size_t)(n >> 6) * M * HDIM + (size_t)m * HDIM + (n & 63)] = v;
            else
                out[(size_t)m * D_MODEL + n] = v;
        }
    }
}

// ---------------------------------------------------------------------------
// Scores: S[h,t,s] = qh[h,t]·kh[h,s] + qh[h,t+1]·Er[s]   (relative-shift fused
// as an augmented K=128 GEMM: A = [qh[t] | qh[t+1]], B = [kh[s] | Er[s]]).
// Causal: blocks entirely above the diagonal are skipped. Entries with s>t in
// diagonal tiles are written but ignored/zeroed by softmax.
// ---------------------------------------------------------------------------
__global__ __launch_bounds__(256)
void scores_kernel(const float* __restrict__ qh, const float* __restrict__ kh,
                   const float* __restrict__ Er, float* __restrict__ S) {
    const int m0 = blockIdx.y * 64;      // t tile
    const int n0 = blockIdx.x * 64;      // s tile
    if (n0 > m0 + 63) return;            // fully masked
    const int h = blockIdx.z;
    const int T = T_SEQ;

    __shared__ float As[16][68];
    __shared__ float Bs[16][68];
    const int tid = threadIdx.x;
    const int tx = tid & 15, ty = tid >> 4;
    const int lrow = tid >> 2;
    const int lk   = (tid & 3) * 4;

    const float* qbase = qh + (size_t)h * T * HDIM;
    const float* kbase = kh + (size_t)h * T * HDIM;
    float acc[4][4] = {};

    for (int k0 = 0; k0 < 128; k0 += 16) {
        const int kq = k0 + lk;          // 0..124, chunk never crosses the 64 boundary
        // A tile: t rows
        float4 va = make_float4(0.f, 0.f, 0.f, 0.f);
        {
            int t = m0 + lrow;
            if (kq < 64) {
                if (t < T) va = *(const float4*)(qbase + (size_t)t * HDIM + kq);
            } else {
                int t2 = t + 1;          // relative-shift: row t uses qh[t+1]
                if (t2 < T) va = *(const float4*)(qbase + (size_t)t2 * HDIM + (kq - 64));
            }
        }
        // B tile: s rows
        float4 vb = make_float4(0.f, 0.f, 0.f, 0.f);
        {
            int s = n0 + lrow;
            if (s < T) {
                if (kq < 64) vb = *(const float4*)(kbase + (size_t)s * HDIM + kq);
                else         vb = *(const float4*)(Er + (size_t)s * HDIM + (kq - 64));
            }
        }
        As[lk+0][lrow] = va.x; As[lk+1][lrow] = va.y;
        As[lk+2][lrow] = va.z; As[lk+3][lrow] = va.w;
        Bs[lk+0][lrow] = vb.x; Bs[lk+1][lrow] = vb.y;
        Bs[lk+2][lrow] = vb.z; Bs[lk+3][lrow] = vb.w;
        __syncthreads();
#pragma unroll
        for (int kk = 0; kk < 16; kk++) {
            float4 a4 = *(const float4*)&As[kk][ty * 4];
            float4 b4 = *(const float4*)&Bs[kk][tx * 4];
            float a[4] = {a4.x, a4.y, a4.z, a4.w};
            float b[4] = {b4.x, b4.y, b4.z, b4.w};
#pragma unroll
            for (int i = 0; i < 4; i++)
#pragma unroll
                for (int j = 0; j < 4; j++)
                    acc[i][j] = fmaf(a[i], b[j], acc[i][j]);
        }
        __syncthreads();
    }

    float* sbase = S + (size_t)h * T * T;
#pragma unroll
    for (int i = 0; i < 4; i++) {
        int t = m0 + ty * 4 + i;
        if (t >= T) continue;
#pragma unroll
        for (int j = 0; j < 4; j++) {
            int s = n0 + tx * 4 + j;
            if (s < T) sbase[(size_t)t * T + s] = acc[i][j];
        }
    }
}

// ---------------------------------------------------------------------------
// Row softmax over s in [0, t] with scale 1/sqrt(64)=0.125, in place.
// Writes exact zeros for s > t so the AV kernel needs no masking.
// ---------------------------------------------------------------------------
__global__ __launch_bounds__(256)
void softmax_kernel(float* __restrict__ S) {
    const int T = T_SEQ;
    const int t = blockIdx.x;
    const int h = blockIdx.y;
    float* r = S + ((size_t)h * T + t) * T;
    const int tid = threadIdx.x;
    __shared__ float red[32];

    float m = -1e30f;
    for (int s = tid; s <= t; s += 256) m = fmaxf(m, r[s]);
#pragma unroll
    for (int o = 16; o; o >>= 1) m = fmaxf(m, __shfl_xor_sync(~0u, m, o));
    if ((tid & 31) == 0) red[tid >> 5] = m;
    __syncthreads();
    if (tid < 32) {
        float v = (tid < 8) ? red[tid] : -1e30f;
#pragma unroll
        for (int o = 4; o; o >>= 1) v = fmaxf(v, __shfl_xor_sync(~0u, v, o));
        if (tid == 0) red[0] = v;
    }
    __syncthreads();
    m = red[0];
    __syncthreads();

    float sum = 0.f;
    for (int s = tid; s <= t; s += 256) {
        float e = __expf((r[s] - m) * 0.125f);
        r[s] = e;
        sum += e;
    }
#pragma unroll
    for (int o = 16; o; o >>= 1) sum += __shfl_xor_sync(~0u, sum, o);
    if ((tid & 31) == 0) red[tid >> 5] = sum;
    __syncthreads();
    if (tid < 32) {
        float v = (tid < 8) ? red[tid] : 0.f;
#pragma unroll
        for (int o = 4; o; o >>= 1) v += __shfl_xor_sync(~0u, v, o);
        if (tid == 0) red[0] = v;
    }
    __syncthreads();
    const float inv = 1.0f / red[0];
    for (int s = tid; s < T; s += 256)
        r[s] = (s <= t) ? r[s] * inv : 0.0f;
}

// ---------------------------------------------------------------------------
// AV: ctx[t, h*64+d] = sum_{s<=t} P[h,t,s] * vh[h,s,d]
// One block per (head, 64-row t-tile); causal-bounded K loop.
// ---------------------------------------------------------------------------
__global__ __launch_bounds__(256)
void av_kernel(const float* __restrict__ S, const float* __restrict__ vh,
               float* __restrict__ ctx) {
    const int T = T_SEQ;
    const int m0 = blockIdx.x * 64;
    const int h  = blockIdx.y;
    const int tid = threadIdx.x;
    const int tx = tid & 15, ty = tid >> 4;

    __shared__ float Ps[16][68];
    __shared__ float Vs[16][68];
    float acc[4][4] = {};

    const float* sbase = S  + (size_t)h * T * T;
    const float* vbase = vh + (size_t)h * T * HDIM;
    const int smax = min(m0 + 63, T - 1);

    const int prow = tid >> 2;           // t-local 0..63
    const int pss  = (tid & 3) * 4;      // s-local base
    const int vsr  = tid >> 4;           // s-local 0..15
    const int vd4  = (tid & 15) * 4;     // d base

    for (int s0 = 0; s0 <= smax; s0 += 16) {
        // P tile (row stride T=2049 is odd -> scalar, guarded loads)
        {
            int t = m0 + prow;
#pragma unroll
            for (int i = 0; i < 4; i++) {
                int s = s0 + pss + i;
                float v = 0.f;
                if (t < T && s < T) v = sbase[(size_t)t * T + s];
                Ps[pss + i][prow] = v;
            }
        }
        // V tile
        {
            int s = s0 + vsr;
            float4 vv = make_float4(0.f, 0.f, 0.f, 0.f);
            if (s < T) vv = *(const float4*)(vbase + (size_t)s * HDIM + vd4);
            Vs[vsr][vd4+0] = vv.x; Vs[vsr][vd4+1] = vv.y;
            Vs[vsr][vd4+2] = vv.z; Vs[vsr][vd4+3] = vv.w;
        }
        __syncthreads();
#pragma unroll
        for (int kk = 0; kk < 16; kk++) {
            float4 a4 = *(const float4*)&Ps[kk][ty * 4];
            float4 b4 = *(const float4*)&Vs[kk][tx * 4];
            float a[4] = {a4.x, a4.y, a4.z, a4.w};
            float b[4] = {b4.x, b4.y, b4.z, b4.w};
#pragma unroll
            for (int i = 0; i < 4; i++)
#pragma unroll
                for (int j = 0; j < 4; j++)
                    acc[i][j] = fmaf(a[i], b[j], acc[i][j]);
        }
        __syncthreads();
    }

#pragma unroll
    for (int i = 0; i < 4; i++) {
        int t = m0 + ty * 4 + i;
        if (t >= T) continue;
#pragma unroll
        for (int j = 0; j < 4; j++) {
            int d = tx * 4 + j;
            ctx[(size_t)t * D_MODEL + h * HDIM + d] = acc[i][j];
        }
    }
}

// ---------------------------------------------------------------------------
// Launch. Inputs (metadata order): q,k,v,mask,Wq_w,Wq_b,Wk_w,Wk_b,Wv_w,Wv_b,
// Er,Wo_w,Wo_b. mask is plain causal tril -> applied implicitly.
// ---------------------------------------------------------------------------
extern "C" void kernel_launch(void* const* d_in, const int* in_sizes, int n_in,
                              void* d_out, int out_size) {
    const float* q    = (const float*)d_in[0];
    const float* k    = (const float*)d_in[1];
    const float* v    = (const float*)d_in[2];
    const float* Wq_w = (const float*)d_in[4];
    const float* Wq_b = (const float*)d_in[5];
    const float* Wk_w = (const float*)d_in[6];
    const float* Wk_b = (const float*)d_in[7];
    const float* Wv_w = (const float*)d_in[8];
    const float* Wv_b = (const float*)d_in[9];
    const float* Er   = (const float*)d_in[10];
    const float* Wo_w = (const float*)d_in[11];
    const float* Wo_b = (const float*)d_in[12];
    float* out = (float*)d_out;

    float *qh, *kh, *vh, *S, *ctx;
    cudaGetSymbolAddress((void**)&qh,  g_qh);
    cudaGetSymbolAddress((void**)&kh,  g_kh);
    cudaGetSymbolAddress((void**)&vh,  g_vh);
    cudaGetSymbolAddress((void**)&S,   g_S);
    cudaGetSymbolAddress((void**)&ctx, g_ctx);

    const int mtiles = (T_SEQ + 63) / 64;    // 33
    dim3 blk(256);

    dim3 gProj(D_MODEL / 64, mtiles);        // (16, 33)
    gemm_nt_kernel<1><<<gProj, blk>>>(q, Wq_w, Wq_b, qh);
    gemm_nt_kernel<1><<<gProj, blk>>>(k, Wk_w, Wk_b, kh);
    gemm_nt_kernel<1><<<gProj, blk>>>(v, Wv_w, Wv_b, vh);

    dim3 gS(mtiles, mtiles, NHEAD);          // (33, 33, 16), upper tiles early-exit
    scores_kernel<<<gS, blk>>>(qh, kh, Er, S);

    dim3 gSm(T_SEQ, NHEAD);
    softmax_kernel<<<gSm, blk>>>(S);

    dim3 gAV(mtiles, NHEAD);
    av_kernel<<<gAV, blk>>>(S, vh, ctx);

    gemm_nt_kernel<0><<<gProj, blk>>>(ctx, Wo_w, Wo_b, out);
}